// round 13
// baseline (speedup 1.0000x reference)
#include <cuda_runtime.h>
#include <cuda_fp16.h>
#include <cstdint>

// =====================================================================
// LocalRNN: B=8, L=2048, D=256, KSIZE=8   (sm_103 portable HMMA path)
// R13: B operands loaded register-direct via LDG.128 from a fragment-
//      layout W image (no SMEM ring, no mbarriers, no LDSM for B).
//      w_prep emits, per (chunk c, n16 group gq), a 512B block where
//      lane l's 16B = {B[k0..k0+1][n0], B[k0+8..9][n0],
//                      same for n0+8}, k0=c*16+2*(l%4), n0=gq*16+l/4
//      == the mma.m16n8k16 B fragment regs (b0,b1) x 2 n8-tiles.
//      A stays LDSM from SMEM. SMEM = U + X/H overlay = 76032 B.
// =====================================================================

namespace {
constexpr int Ll = 2048, Dd = 256, Ks = 8, ROWS = 16384;
constexpr int NCH  = 16;               // k-chunks of 16
constexpr int HSTR = 264;              // row stride in halfs (padded)
constexpr int TM   = 64;               // output rows per CTA
constexpr int NT   = 256;              // 8 warps, n-slice 32 each
constexpr int UROWS = 72;              // U rows incl. 8 boundary rows
constexpr int UIMG  = UROWS * HSTR * 2;            // 38016
constexpr int XOFF  = UIMG;                        // X (phase A) / H (phase B)
constexpr int SMEM_DYN = XOFF + UIMG;              // 76032
}

// Fragment-layout W images: (c*16+gq)*512 + lane*16
__device__ __align__(16) __half g_Wf[NCH * 4096];
__device__ __align__(16) __half g_WIf[NCH * 4096];
__device__ float g_itau[Dd];

// ------------------------- PTX helpers --------------------------------
__device__ __forceinline__ uint32_t smem_u32(const void* p) {
    uint32_t a;
    asm("{ .reg .u64 t; cvta.to.shared.u64 t, %1; cvt.u32.u64 %0, t; }"
        : "=r"(a) : "l"(p));
    return a;
}

#define LDSM_X4(r, addr)                                                      \
    asm volatile("ldmatrix.sync.aligned.m8n8.x4.shared.b16 "                  \
                 "{%0,%1,%2,%3}, [%4];"                                       \
                 : "=r"((r)[0]), "=r"((r)[1]), "=r"((r)[2]), "=r"((r)[3])     \
                 : "r"(addr))

#define MMAH(d, a, b0_, b1_)                                                  \
    asm volatile(                                                             \
        "mma.sync.aligned.m16n8k16.row.col.f32.f16.f16.f32 "                  \
        "{%0,%1,%2,%3},{%4,%5,%6,%7},{%8,%9},{%0,%1,%2,%3};"                  \
        : "+f"((d)[0]), "+f"((d)[1]), "+f"((d)[2]), "+f"((d)[3])              \
        : "r"((a)[0]), "r"((a)[1]), "r"((a)[2]), "r"((a)[3]),                 \
          "r"(b0_), "r"(b1_))

__device__ __forceinline__ uint32_t pack_hi(float x, float y) {
    __half2 p = __floats2half2_rn(x, y);
    return *(uint32_t*)&p;
}

// ====================== k0: W prep (fragment layout) ==================
__global__ __launch_bounds__(256) void w_prep_kernel(const float* __restrict__ W,
                                                     const float* __restrict__ Win,
                                                     const float* __restrict__ tau) {
    __shared__ float tile[16][256];
    const int c   = blockIdx.x >> 1;
    const int m   = blockIdx.x & 1;
    const int tid = threadIdx.x;
    const float* src = m ? Win : W;
    __half* dst = m ? g_WIf : g_Wf;
    if (blockIdx.x == 0 && tid < Dd) g_itau[tid] = 1.0f / tau[tid];

#pragma unroll
    for (int kk = 0; kk < 16; kk++)
        tile[kk][tid] = src[(size_t)(c * 16 + kk) * Dd + tid];
    __syncthreads();

    const int w = tid >> 5, l = tid & 31;
    const int k0 = (l & 3) * 2;
#pragma unroll
    for (int gsel = 0; gsel < 2; gsel++) {
        const int gq = w + gsel * 8;
        const int n0 = gq * 16 + (l >> 2);
        __half h8[8];
        h8[0] = __float2half_rn(tile[k0][n0]);
        h8[1] = __float2half_rn(tile[k0 + 1][n0]);
        h8[2] = __float2half_rn(tile[k0 + 8][n0]);
        h8[3] = __float2half_rn(tile[k0 + 9][n0]);
        h8[4] = __float2half_rn(tile[k0][n0 + 8]);
        h8[5] = __float2half_rn(tile[k0 + 1][n0 + 8]);
        h8[6] = __float2half_rn(tile[k0 + 8][n0 + 8]);
        h8[7] = __float2half_rn(tile[k0 + 9][n0 + 8]);
        *(uint4*)((char*)dst + (size_t)(c * 16 + gq) * 512 + l * 16) =
            *(uint4*)h8;
    }
}

// ====================== k1: fused U-GEMM + RNN ========================
__global__ __launch_bounds__(NT, 2) void fused_kernel(const float* __restrict__ X,
                                                      const float* __restrict__ bias,
                                                      float* __restrict__ out) {
    extern __shared__ __align__(128) char dsmem[];

    const int tid = threadIdx.x;
    const int wid = tid >> 5;           // 0..7 -> n-slice wid*32
    const int t   = tid & 31;

    const uint32_t base = smem_u32(dsmem);
    const uint32_t xs   = base + XOFF;       // X image (phase A)
    const uint32_t hs   = base + XOFF;       // H image (phase B, same region)
    const int r0 = blockIdx.x * TM;

    // W images as uint4 blocks: index (c*16+gq)*32 + lane
    const uint4* __restrict__ WIv = (const uint4*)g_WIf;
    const uint4* __restrict__ Wv  = (const uint4*)g_Wf;
    const int bidx = wid * 2 * 32 + t;       // lane slot for gq = 2*wid

    // ---- load X rows 0..71 (global r0-8+xi), convert to fp16 ----
    for (int xi = wid; xi < UROWS; xi += 8) {
        long gxr = (long)r0 - 8 + xi;
        if (gxr < 0) gxr = 0;                 // values unused when invalid
        const float* xr = X + (size_t)gxr * Dd;
        const int c = t * 8;
        float4 v0 = *(const float4*)(xr + c);
        float4 v1 = *(const float4*)(xr + c + 4);
        uint32_t p[4] = {pack_hi(v0.x, v0.y), pack_hi(v0.z, v0.w),
                         pack_hi(v1.x, v1.y), pack_hi(v1.z, v1.w)};
        *(uint4*)(dsmem + XOFF + (size_t)(xi * HSTR + c) * 2) = *(uint4*)p;
    }
    __syncthreads();

    const int a_r  = ((t >> 3) & 1) * 8 + (t & 7);
    const int a_k  = ((t >> 4) & 1) * 8;

    // =================== Phase A: U = X @ Win + bias ==================
    {
        float D[4][4][4];           // main m64 x n32
        float Ds[4][4];             // strip m16 x n32
#pragma unroll
        for (int i = 0; i < 4; i++)
#pragma unroll
            for (int j = 0; j < 4; j++)
#pragma unroll
                for (int q = 0; q < 4; q++) D[i][j][q] = 0.f;
#pragma unroll
        for (int j = 0; j < 4; j++)
#pragma unroll
            for (int q = 0; q < 4; q++) Ds[j][q] = 0.f;

        uint4 bA = __ldg(WIv + bidx);
        uint4 bB = __ldg(WIv + bidx + 32);

#pragma unroll
        for (int g = 0; g < NCH; g++) {
            uint4 nA, nB;
            if (g < NCH - 1) {
                nA = __ldg(WIv + (g + 1) * 512 + bidx);
                nB = __ldg(WIv + (g + 1) * 512 + bidx + 32);
            }
            uint32_t AH[4][4], As[4];
            const int kc = g * 16;
#pragma unroll
            for (int i = 0; i < 4; i++) {
                uint32_t off =
                    (uint32_t)((8 + i * 16 + a_r) * HSTR + kc + a_k) * 2;
                LDSM_X4(AH[i], xs + off);
            }
            LDSM_X4(As, xs + (uint32_t)(a_r * HSTR + kc + a_k) * 2);

#pragma unroll
            for (int i = 0; i < 4; i++) {
                MMAH(D[i][0], AH[i], bA.x, bA.y);
                MMAH(D[i][1], AH[i], bA.z, bA.w);
                MMAH(D[i][2], AH[i], bB.x, bB.y);
                MMAH(D[i][3], AH[i], bB.z, bB.w);
            }
            MMAH(Ds[0], As, bA.x, bA.y);
            MMAH(Ds[1], As, bA.z, bA.w);
            MMAH(Ds[2], As, bB.x, bB.y);
            MMAH(Ds[3], As, bB.z, bB.w);

            bA = nA; bB = nB;
        }

        // ---- epilogue A: U = D + bias -> SMEM fp16 ----
#pragma unroll
        for (int i = 0; i < 4; i++) {
#pragma unroll
            for (int half = 0; half < 2; half++) {
                const int ru = 8 + i * 16 + (t >> 2) + half * 8;
#pragma unroll
                for (int j = 0; j < 4; j++) {
                    const int cc = wid * 32 + j * 8 + 2 * (t & 3);
                    float2 b = *(const float2*)(bias + cc);
                    *(uint32_t*)(dsmem + (size_t)(ru * HSTR + cc) * 2) =
                        pack_hi(D[i][j][half * 2] + b.x,
                                D[i][j][half * 2 + 1] + b.y);
                }
            }
        }
        // strip rows 0..15 (rows 8..15 double-written, identical bits)
#pragma unroll
        for (int half = 0; half < 2; half++) {
            const int ru = (t >> 2) + half * 8;
#pragma unroll
            for (int j = 0; j < 4; j++) {
                const int cc = wid * 32 + j * 8 + 2 * (t & 3);
                float2 b = *(const float2*)(bias + cc);
                *(uint32_t*)(dsmem + (size_t)(ru * HSTR + cc) * 2) =
                    pack_hi(Ds[j][half * 2] + b.x,
                            Ds[j][half * 2 + 1] + b.y);
            }
        }
    }
    __syncthreads();   // U complete; X image dead

    // ---- step 0: h1 = itau * relu(u_{l-7})  (U image row rr+1) ----
    for (int rr = wid; rr < TM; rr += 8) {
        const int gr = r0 + rr;
        const int l  = gr & (Ll - 1);
        const int c  = t * 8;
        float u[8];
        if (l >= Ks - 1) {
            uint4 up = *(uint4*)(dsmem + (size_t)((rr + 1) * HSTR + c) * 2);
            uint32_t uw[4] = {up.x, up.y, up.z, up.w};
#pragma unroll
            for (int q = 0; q < 4; q++) {
                __half2 h2 = *(__half2*)&uw[q];
                u[2 * q]     = __half2float(__low2half(h2));
                u[2 * q + 1] = __half2float(__high2half(h2));
            }
        } else {
            float4 b0 = *(const float4*)(bias + c);
            float4 b1 = *(const float4*)(bias + c + 4);
            u[0] = b0.x; u[1] = b0.y; u[2] = b0.z; u[3] = b0.w;
            u[4] = b1.x; u[5] = b1.y; u[6] = b1.z; u[7] = b1.w;
        }
        float4 i0 = *(const float4*)(g_itau + c);
        float4 i1 = *(const float4*)(g_itau + c + 4);
        float it[8] = {i0.x, i0.y, i0.z, i0.w, i1.x, i1.y, i1.z, i1.w};
        uint32_t p[4];
#pragma unroll
        for (int q = 0; q < 4; q++)
            p[q] = pack_hi(it[2 * q] * fmaxf(u[2 * q], 0.f),
                           it[2 * q + 1] * fmaxf(u[2 * q + 1], 0.f));
        *(uint4*)(dsmem + XOFF + (size_t)(rr * HSTR + c) * 2) = *(uint4*)p;
    }
    __syncthreads();

    // =================== Phase B: 7-step recurrence ===================
    for (int step = 1; step < Ks; step++) {
        float D[4][4][4];
#pragma unroll
        for (int i = 0; i < 4; i++)
#pragma unroll
            for (int j = 0; j < 4; j++)
#pragma unroll
                for (int q = 0; q < 4; q++) D[i][j][q] = 0.f;

        uint4 bA = __ldg(Wv + bidx);
        uint4 bB = __ldg(Wv + bidx + 32);

#pragma unroll
        for (int c = 0; c < NCH; c++) {
            uint4 nA, nB;
            if (c < NCH - 1) {
                nA = __ldg(Wv + (c + 1) * 512 + bidx);
                nB = __ldg(Wv + (c + 1) * 512 + bidx + 32);
            }
            uint32_t AH[4][4];
            const int kc = c * 16;
#pragma unroll
            for (int i = 0; i < 4; i++) {
                uint32_t off =
                    (uint32_t)((i * 16 + a_r) * HSTR + kc + a_k) * 2;
                LDSM_X4(AH[i], hs + off);
            }

#pragma unroll
            for (int i = 0; i < 4; i++) {
                MMAH(D[i][0], AH[i], bA.x, bA.y);
                MMAH(D[i][1], AH[i], bA.z, bA.w);
                MMAH(D[i][2], AH[i], bB.x, bB.y);
                MMAH(D[i][3], AH[i], bB.z, bB.w);
            }
            bA = nA; bB = nB;
        }
        __syncthreads();   // all A-reads of H done before epilogue writes

        // ---- fused epilogue: h' = h + itau*(relu(D+u) - h) ----
        const bool last = (step == Ks - 1);
#pragma unroll
        for (int i = 0; i < 4; i++) {
#pragma unroll
            for (int half = 0; half < 2; half++) {
                const int rl = i * 16 + (t >> 2) + half * 8;
                const int gr = r0 + rl;
                const int tt = (gr & (Ll - 1)) - (Ks - 1) + step;
                const int ur = rl + step + 1;      // U image row (<= 71)
#pragma unroll
                for (int j = 0; j < 4; j++) {
                    const int cc = wid * 32 + j * 8 + 2 * (t & 3);
                    float2 u;
                    if (tt >= 0) {
                        uint32_t uv =
                            *(uint32_t*)(dsmem + (size_t)(ur * HSTR + cc) * 2);
                        __half2 uh = *(__half2*)&uv;
                        u = make_float2(__half2float(__low2half(uh)),
                                        __half2float(__high2half(uh)));
                    } else {
                        u = *(const float2*)(bias + cc);
                    }
                    float2 it = *(const float2*)(g_itau + cc);
                    const float d0 = D[i][j][half * 2];
                    const float d1 = D[i][j][half * 2 + 1];
                    char* hb = dsmem + XOFF + (size_t)(rl * HSTR + cc) * 2;
                    uint32_t hv = *(uint32_t*)(hb);
                    __half2 hh = *(__half2*)&hv;
                    float h0 = __half2float(__low2half(hh));
                    float h1 = __half2float(__high2half(hh));
                    float s0 = fmaxf(d0 + u.x, 0.f);
                    float s1 = fmaxf(d1 + u.y, 0.f);
                    float n0 = h0 + it.x * (s0 - h0);
                    float n1 = h1 + it.y * (s1 - h1);
                    if (last) {
                        *(float2*)(out + (size_t)gr * Dd + cc) =
                            make_float2(n0, n1);
                    } else {
                        *(uint32_t*)(hb) = pack_hi(n0, n1);
                    }
                }
            }
        }
        if (!last) __syncthreads();
    }
}

// ---------------------------------------------------------------------------
extern "C" void kernel_launch(void* const* d_in, const int* in_sizes, int n_in,
                              void* d_out, int out_size) {
    (void)in_sizes; (void)n_in; (void)out_size;
    const float* x            = (const float*)d_in[0];
    const float* weight       = (const float*)d_in[1];
    const float* input_weight = (const float*)d_in[2];
    const float* bias         = (const float*)d_in[3];
    const float* tau          = (const float*)d_in[4];
    float* out = (float*)d_out;

    w_prep_kernel<<<2 * NCH, 256>>>(weight, input_weight, tau);

    cudaFuncSetAttribute(fused_kernel, cudaFuncAttributeMaxDynamicSharedMemorySize,
                         SMEM_DYN);
    fused_kernel<<<ROWS / TM, NT, SMEM_DYN>>>(x, bias, out);
}

// round 14
// speedup vs baseline: 1.2109x; 1.2109x over previous
#include <cuda_runtime.h>
#include <cuda_fp16.h>
#include <cstdint>

// =====================================================================
// LocalRNN: B=8, L=2048, D=256, KSIZE=8   (sm_103 portable HMMA path)
// R14: base = R12 (best: 68.1us). Ring reorganized as 2 groups x 2
//      chunks with ONE full/empty mbarrier pair per group -> waits and
//      arrives per step halved (16 -> 8 per warp). B double-buffer
//      prefetch kept. 16 warps/SM (2 CTAs x 8 warps), numerics same.
// SMEM:  [U 38016)[X|H 38016)[ring 2x16384)  = 108800 -> 2 CTAs/SM
// =====================================================================

namespace {
constexpr int Ll = 2048, Dd = 256, Ks = 8, ROWS = 16384;
constexpr int NCH  = 16;               // k-chunks of 16
constexpr int WCH  = 8192;             // packed chunk image: 256n x 32B
constexpr int GRPB = 2 * WCH;          // group = 2 chunks = 16384 B
constexpr int HSTR = 264;              // row stride in halfs (padded)
constexpr int TM   = 64;               // output rows per CTA
constexpr int NT   = 256;              // 8 warps, n-slice 32 each
constexpr int UROWS = 72;              // U rows incl. 8 boundary rows
constexpr int UIMG  = UROWS * HSTR * 2;            // 38016
constexpr int XOFF  = UIMG;
constexpr int HOFF  = UIMG;
constexpr int RINGOFF = XOFF + UIMG;               // 76032
constexpr int SMEM_DYN = RINGOFF + 2 * GRPB;       // 108800
constexpr int GTOT = (Ks - 1) * NCH;               // 112 W chunk-uses
}

__device__ __align__(16) __half g_Wf[NCH * 4096];
__device__ __align__(16) __half g_WIf[NCH * 4096];
__device__ float g_itau[Dd];

// ------------------------- PTX helpers --------------------------------
__device__ __forceinline__ uint32_t smem_u32(const void* p) {
    uint32_t a;
    asm("{ .reg .u64 t; cvta.to.shared.u64 t, %1; cvt.u32.u64 %0, t; }"
        : "=r"(a) : "l"(p));
    return a;
}

#define MBARRIER_INIT(mbar, cnt) \
    asm volatile("mbarrier.init.shared.b64 [%0], %1;" \
                 :: "r"((uint32_t)(mbar)), "r"((uint32_t)(cnt)) : "memory")
#define MBARRIER_ARRIVE(mbar) \
    asm volatile("mbarrier.arrive.shared.b64 _, [%0];" \
                 :: "r"((uint32_t)(mbar)) : "memory")
#define MBARRIER_EXPECT_TX(mbar, bytes) \
    asm volatile("mbarrier.arrive.expect_tx.shared.b64 _, [%0], %1;" \
                 :: "r"((uint32_t)(mbar)), "r"((uint32_t)(bytes)) : "memory")
#define MBARRIER_WAIT_PARITY(mbar, parity) do {                               \
    uint32_t _m = (uint32_t)(mbar);                                           \
    uint32_t _p = (uint32_t)(parity);                                         \
    uint32_t _done;                                                           \
    asm volatile(                                                             \
        "{\n\t.reg .pred p;\n\t"                                              \
        "mbarrier.try_wait.parity.acquire.cta.shared::cta.b64 p, [%1], %2;\n\t" \
        "selp.b32 %0, 1, 0, p;\n\t}"                                          \
        : "=r"(_done) : "r"(_m), "r"(_p) : "memory");                         \
    if (!_done) {                                                             \
        asm volatile(                                                         \
            "{\n\t.reg .pred P1;\n\t"                                         \
            "WL_%=:\n\t"                                                      \
            "mbarrier.try_wait.parity.acquire.cta.shared::cta.b64 P1, [%0], %1, 0x989680;\n\t" \
            "@P1 bra.uni WD_%=;\n\t"                                          \
            "bra.uni WL_%=;\n\t"                                              \
            "WD_%=:\n\t}"                                                     \
            :: "r"(_m), "r"(_p) : "memory");                                  \
    }                                                                         \
} while (0)

#define BULK_G2S(dst, src, bytes, mbar)                                       \
    asm volatile(                                                             \
        "cp.async.bulk.shared::cluster.global.mbarrier::complete_tx::bytes "  \
        "[%0], [%1], %2, [%3];"                                               \
        :: "r"((uint32_t)(dst)), "l"(src), "r"((uint32_t)(bytes)),            \
           "r"((uint32_t)(mbar)) : "memory")

#define LDSM_X4(r, addr)                                                      \
    asm volatile("ldmatrix.sync.aligned.m8n8.x4.shared.b16 "                  \
                 "{%0,%1,%2,%3}, [%4];"                                       \
                 : "=r"((r)[0]), "=r"((r)[1]), "=r"((r)[2]), "=r"((r)[3])     \
                 : "r"(addr))

#define MMAH(d, a, b0_, b1_)                                                  \
    asm volatile(                                                             \
        "mma.sync.aligned.m16n8k16.row.col.f32.f16.f16.f32 "                  \
        "{%0,%1,%2,%3},{%4,%5,%6,%7},{%8,%9},{%0,%1,%2,%3};"                  \
        : "+f"((d)[0]), "+f"((d)[1]), "+f"((d)[2]), "+f"((d)[3])              \
        : "r"((a)[0]), "r"((a)[1]), "r"((a)[2]), "r"((a)[3]),                 \
          "r"(b0_), "r"(b1_))

__device__ __forceinline__ uint32_t pack_hi(float x, float y) {
    __half2 p = __floats2half2_rn(x, y);
    return *(uint32_t*)&p;
}

// ====================== k0: W prep (32B rows, XOR swizzle) ============
__global__ __launch_bounds__(256) void w_prep_kernel(const float* __restrict__ W,
                                                     const float* __restrict__ Win,
                                                     const float* __restrict__ tau) {
    __shared__ float tile[16][256];
    const int c   = blockIdx.x >> 1;
    const int m   = blockIdx.x & 1;
    const int tid = threadIdx.x;         // = n
    const float* src = m ? Win : W;
    __half* dst = m ? g_WIf : g_Wf;
    if (blockIdx.x == 0 && tid < Dd) g_itau[tid] = 1.0f / tau[tid];

#pragma unroll
    for (int kk = 0; kk < 16; kk++)
        tile[kk][tid] = src[(size_t)(c * 16 + kk) * Dd + tid];
    __syncthreads();

    const uint32_t nsw = ((uint32_t)(tid >> 2) & 1u);
#pragma unroll
    for (int kh = 0; kh < 2; kh++) {
        uint32_t off = (uint32_t)c * 8192u + (uint32_t)tid * 32u +
                       (((uint32_t)kh ^ nsw) << 4);
        __half h8[8];
#pragma unroll
        for (int j = 0; j < 8; j++)
            h8[j] = __float2half_rn(tile[kh * 8 + j][tid]);
        *(uint4*)((char*)dst + off) = *(uint4*)h8;
    }
}

// ====================== k1: fused U-GEMM + RNN ========================
__global__ __launch_bounds__(NT, 2) void fused_kernel(const float* __restrict__ X,
                                                      const float* __restrict__ bias,
                                                      float* __restrict__ out) {
    extern __shared__ __align__(128) char dsmem[];
    __shared__ __align__(8) uint64_t s_wif[2], s_wie[2];   // phase A group barriers
    __shared__ __align__(8) uint64_t s_wf[2],  s_we[2];    // phase B group barriers

    const int tid = threadIdx.x;
    const int wid = tid >> 5;           // 0..7 -> n-slice wid*32
    const int t   = tid & 31;

    const uint32_t base = smem_u32(dsmem);
    const uint32_t xs   = base + XOFF;
    const uint32_t hs   = base + HOFF;
    const uint32_t ring = base + RINGOFF;
    const uint32_t mwf = smem_u32(s_wif), mwe = smem_u32(s_wie);
    const uint32_t mf  = smem_u32(s_wf),  me  = smem_u32(s_we);
    const int r0 = blockIdx.x * TM;

    if (tid == 0) {
        for (int i = 0; i < 2; i++) {
            MBARRIER_INIT(mwf + i * 8, 1);
            MBARRIER_INIT(mwe + i * 8, 8);
            MBARRIER_INIT(mf + i * 8, 1);
            MBARRIER_INIT(me + i * 8, 8);
        }
    }
    __syncthreads();

    // Prime phase-A ring: groups 0,1 (Win chunks 0..3)
    if (tid == 0) {
#pragma unroll
        for (int s = 0; s < 2; s++) {
            MBARRIER_EXPECT_TX(mwf + s * 8, GRPB);
            BULK_G2S(ring + s * GRPB,       (const char*)g_WIf + (2 * s) * WCH,
                     WCH, mwf + s * 8);
            BULK_G2S(ring + s * GRPB + WCH, (const char*)g_WIf + (2 * s + 1) * WCH,
                     WCH, mwf + s * 8);
        }
    }

    // ---- load X rows 0..71 (global r0-8+xi), convert to fp16 ----
    for (int xi = wid; xi < UROWS; xi += 8) {
        long gxr = (long)r0 - 8 + xi;
        if (gxr < 0) gxr = 0;                 // values unused when invalid
        const float* xr = X + (size_t)gxr * Dd;
        const int c = t * 8;
        float4 v0 = *(const float4*)(xr + c);
        float4 v1 = *(const float4*)(xr + c + 4);
        uint32_t p[4] = {pack_hi(v0.x, v0.y), pack_hi(v0.z, v0.w),
                         pack_hi(v1.x, v1.y), pack_hi(v1.z, v1.w)};
        *(uint4*)(dsmem + XOFF + (size_t)(xi * HSTR + c) * 2) = *(uint4*)p;
    }
    __syncthreads();

    const int a_r  = ((t >> 3) & 1) * 8 + (t & 7);
    const int a_k  = ((t >> 4) & 1) * 8;
    const int b_n  = ((t >> 4) & 1) * 8 + (t & 7);
    const int kh   = (t >> 3) & 1;
    const int nbase = wid * 32 + b_n;
    const uint32_t sw16 = ((((uint32_t)nbase >> 2) & 1u) ^ (uint32_t)kh) << 4;
    const uint32_t boff = (uint32_t)nbase * 32 + sw16;   // lane offset in chunk

    // =================== Phase A: U = X @ Win + bias ==================
    {
        float D[4][4][4];           // main m64 x n32
        float Ds[4][4];             // strip m16 x n32
#pragma unroll
        for (int i = 0; i < 4; i++)
#pragma unroll
            for (int j = 0; j < 4; j++)
#pragma unroll
                for (int q = 0; q < 4; q++) D[i][j][q] = 0.f;
#pragma unroll
        for (int j = 0; j < 4; j++)
#pragma unroll
            for (int q = 0; q < 4; q++) Ds[j][q] = 0.f;

        for (int g = 0; g < NCH; g++) {
            const int G = g >> 1;            // group 0..7
            if ((g & 1) == 0)
                MBARRIER_WAIT_PARITY(mwf + (G & 1) * 8, (G >> 1) & 1);

            uint32_t AH[4][4], As[4];
            const int kc = g * 16;
#pragma unroll
            for (int i = 0; i < 4; i++) {
                uint32_t off =
                    (uint32_t)((8 + i * 16 + a_r) * HSTR + kc + a_k) * 2;
                LDSM_X4(AH[i], xs + off);
            }
            LDSM_X4(As, xs + (uint32_t)(a_r * HSTR + kc + a_k) * 2);

            const uint32_t sb = ring + (uint32_t)(G & 1) * GRPB +
                                (uint32_t)(g & 1) * WCH;
            uint32_t BH[2][4];
            LDSM_X4(BH[0], sb + boff);
            LDSM_X4(BH[1], sb + boff + 16 * 32);

            if (g & 1) {                     // group's ring reads done
                __syncwarp();
                if (t == 0) MBARRIER_ARRIVE(mwe + (G & 1) * 8);
                if (tid == 0 && G + 2 < 8) {
                    MBARRIER_WAIT_PARITY(mwe + (G & 1) * 8, (G >> 1) & 1);
                    const int cp = (G + 2) * 2;
                    MBARRIER_EXPECT_TX(mwf + (G & 1) * 8, GRPB);
                    BULK_G2S(ring + (G & 1) * GRPB,
                             (const char*)g_WIf + cp * WCH, WCH,
                             mwf + (G & 1) * 8);
                    BULK_G2S(ring + (G & 1) * GRPB + WCH,
                             (const char*)g_WIf + (cp + 1) * WCH, WCH,
                             mwf + (G & 1) * 8);
                }
            }

#pragma unroll
            for (int jp = 0; jp < 2; jp++) {
#pragma unroll
                for (int i = 0; i < 4; i++) {
                    MMAH(D[i][2 * jp],     AH[i], BH[jp][0], BH[jp][1]);
                    MMAH(D[i][2 * jp + 1], AH[i], BH[jp][2], BH[jp][3]);
                }
                MMAH(Ds[2 * jp],     As, BH[jp][0], BH[jp][1]);
                MMAH(Ds[2 * jp + 1], As, BH[jp][2], BH[jp][3]);
            }
        }

        // ---- epilogue A: U = D + bias -> SMEM fp16 ----
#pragma unroll
        for (int i = 0; i < 4; i++) {
#pragma unroll
            for (int half = 0; half < 2; half++) {
                const int ru = 8 + i * 16 + (t >> 2) + half * 8;
#pragma unroll
                for (int j = 0; j < 4; j++) {
                    const int cc = wid * 32 + j * 8 + 2 * (t & 3);
                    float2 b = *(const float2*)(bias + cc);
                    *(uint32_t*)(dsmem + (size_t)(ru * HSTR + cc) * 2) =
                        pack_hi(D[i][j][half * 2] + b.x,
                                D[i][j][half * 2 + 1] + b.y);
                }
            }
        }
        // strip rows 0..15 (rows 8..15 double-written, identical bits)
#pragma unroll
        for (int half = 0; half < 2; half++) {
            const int ru = (t >> 2) + half * 8;
#pragma unroll
            for (int j = 0; j < 4; j++) {
                const int cc = wid * 32 + j * 8 + 2 * (t & 3);
                float2 b = *(const float2*)(bias + cc);
                *(uint32_t*)(dsmem + (size_t)(ru * HSTR + cc) * 2) =
                    pack_hi(Ds[j][half * 2] + b.x,
                            Ds[j][half * 2 + 1] + b.y);
            }
        }
    }
    __syncthreads();   // U complete; X + Win ring dead

    // Prime phase-B ring: groups 0,1 (W chunks 0..3)
    if (tid == 0) {
#pragma unroll
        for (int s = 0; s < 2; s++) {
            MBARRIER_EXPECT_TX(mf + s * 8, GRPB);
            BULK_G2S(ring + s * GRPB,       (const char*)g_Wf + (2 * s) * WCH,
                     WCH, mf + s * 8);
            BULK_G2S(ring + s * GRPB + WCH, (const char*)g_Wf + (2 * s + 1) * WCH,
                     WCH, mf + s * 8);
        }
    }

    // ---- step 0: h1 = itau * relu(u_{l-7})  (U image row rr+1) ----
    for (int rr = wid; rr < TM; rr += 8) {
        const int gr = r0 + rr;
        const int l  = gr & (Ll - 1);
        const int c  = t * 8;
        float u[8];
        if (l >= Ks - 1) {
            uint4 up = *(uint4*)(dsmem + (size_t)((rr + 1) * HSTR + c) * 2);
            uint32_t uw[4] = {up.x, up.y, up.z, up.w};
#pragma unroll
            for (int q = 0; q < 4; q++) {
                __half2 h2 = *(__half2*)&uw[q];
                u[2 * q]     = __half2float(__low2half(h2));
                u[2 * q + 1] = __half2float(__high2half(h2));
            }
        } else {
            float4 b0 = *(const float4*)(bias + c);
            float4 b1 = *(const float4*)(bias + c + 4);
            u[0] = b0.x; u[1] = b0.y; u[2] = b0.z; u[3] = b0.w;
            u[4] = b1.x; u[5] = b1.y; u[6] = b1.z; u[7] = b1.w;
        }
        float4 i0 = *(const float4*)(g_itau + c);
        float4 i1 = *(const float4*)(g_itau + c + 4);
        float it[8] = {i0.x, i0.y, i0.z, i0.w, i1.x, i1.y, i1.z, i1.w};
        uint32_t p[4];
#pragma unroll
        for (int q = 0; q < 4; q++)
            p[q] = pack_hi(it[2 * q] * fmaxf(u[2 * q], 0.f),
                           it[2 * q + 1] * fmaxf(u[2 * q + 1], 0.f));
        *(uint4*)(dsmem + HOFF + (size_t)(rr * HSTR + c) * 2) = *(uint4*)p;
    }
    __syncthreads();

    // =================== Phase B: 7-step recurrence ===================
    int gg = 0;   // continuous chunk counter 0..111 (groups of 2)
    for (int step = 1; step < Ks; step++) {
        float D[4][4][4];
#pragma unroll
        for (int i = 0; i < 4; i++)
#pragma unroll
            for (int j = 0; j < 4; j++)
#pragma unroll
                for (int q = 0; q < 4; q++) D[i][j][q] = 0.f;

        uint32_t BH[2][2][4];    // double-buffered B fragments

        // prologue: gg is group-aligned (multiple of 16) -> even chunk
        {
            const int G = gg >> 1;
            MBARRIER_WAIT_PARITY(mf + (G & 1) * 8, (G >> 1) & 1);
            const uint32_t sb = ring + (uint32_t)(G & 1) * GRPB;  // sub 0
            LDSM_X4(BH[0][0], sb + boff);
            LDSM_X4(BH[0][1], sb + boff + 16 * 32);
        }

        for (int c = 0; c < NCH; c++, gg++) {
            const int cur = c & 1;
            // prefetch B for chunk gg+1
            if (c < NCH - 1) {
                const int g1 = gg + 1;
                const int G1 = g1 >> 1;
                if ((g1 & 1) == 0)   // entering a new group
                    MBARRIER_WAIT_PARITY(mf + (G1 & 1) * 8, (G1 >> 1) & 1);
                const uint32_t sb1 = ring + (uint32_t)(G1 & 1) * GRPB +
                                     (uint32_t)(g1 & 1) * WCH;
                LDSM_X4(BH[cur ^ 1][0], sb1 + boff);
                LDSM_X4(BH[cur ^ 1][1], sb1 + boff + 16 * 32);
                if (g1 & 1) {        // loaded odd chunk -> group done
                    __syncwarp();
                    if (t == 0) MBARRIER_ARRIVE(me + (G1 & 1) * 8);
                    if (tid == 0 && (G1 + 2) * 2 < GTOT) {
                        MBARRIER_WAIT_PARITY(me + (G1 & 1) * 8, (G1 >> 1) & 1);
                        const int cp = ((G1 + 2) * 2) & 15;
                        MBARRIER_EXPECT_TX(mf + (G1 & 1) * 8, GRPB);
                        BULK_G2S(ring + (G1 & 1) * GRPB,
                                 (const char*)g_Wf + cp * WCH, WCH,
                                 mf + (G1 & 1) * 8);
                        BULK_G2S(ring + (G1 & 1) * GRPB + WCH,
                                 (const char*)g_Wf + (cp + 1) * WCH, WCH,
                                 mf + (G1 & 1) * 8);
                    }
                }
            }

            // A fragments for chunk c
            uint32_t AH[4][4];
            const int kc = c * 16;
#pragma unroll
            for (int i = 0; i < 4; i++) {
                uint32_t off =
                    (uint32_t)((i * 16 + a_r) * HSTR + kc + a_k) * 2;
                LDSM_X4(AH[i], hs + off);
            }

#pragma unroll
            for (int jp = 0; jp < 2; jp++)
#pragma unroll
                for (int i = 0; i < 4; i++) {
                    MMAH(D[i][2 * jp],     AH[i], BH[cur][jp][0], BH[cur][jp][1]);
                    MMAH(D[i][2 * jp + 1], AH[i], BH[cur][jp][2], BH[cur][jp][3]);
                }
        }
        __syncthreads();   // all A-reads of H done before epilogue writes

        // ---- fused epilogue: h' = h + itau*(relu(D+u) - h) ----
        const bool last = (step == Ks - 1);
#pragma unroll
        for (int i = 0; i < 4; i++) {
#pragma unroll
            for (int half = 0; half < 2; half++) {
                const int rl = i * 16 + (t >> 2) + half * 8;
                const int gr = r0 + rl;
                const int tt = (gr & (Ll - 1)) - (Ks - 1) + step;
                const int ur = rl + step + 1;      // U image row (<= 71)
#pragma unroll
                for (int j = 0; j < 4; j++) {
                    const int cc = wid * 32 + j * 8 + 2 * (t & 3);
                    float2 u;
                    if (tt >= 0) {
                        uint32_t uv =
                            *(uint32_t*)(dsmem + (size_t)(ur * HSTR + cc) * 2);
                        __half2 uh = *(__half2*)&uv;
                        u = make_float2(__half2float(__low2half(uh)),
                                        __half2float(__high2half(uh)));
                    } else {
                        u = *(const float2*)(bias + cc);
                    }
                    float2 it = *(const float2*)(g_itau + cc);
                    const float d0 = D[i][j][half * 2];
                    const float d1 = D[i][j][half * 2 + 1];
                    char* hb = dsmem + HOFF + (size_t)(rl * HSTR + cc) * 2;
                    uint32_t hv = *(uint32_t*)(hb);
                    __half2 hh = *(__half2*)&hv;
                    float h0 = __half2float(__low2half(hh));
                    float h1 = __half2float(__high2half(hh));
                    float s0 = fmaxf(d0 + u.x, 0.f);
                    float s1 = fmaxf(d1 + u.y, 0.f);
                    float n0 = h0 + it.x * (s0 - h0);
                    float n1 = h1 + it.y * (s1 - h1);
                    if (last) {
                        *(float2*)(out + (size_t)gr * Dd + cc) =
                            make_float2(n0, n1);
                    } else {
                        *(uint32_t*)(hb) = pack_hi(n0, n1);
                    }
                }
            }
        }
        if (!last) __syncthreads();
    }
}

// ---------------------------------------------------------------------------
extern "C" void kernel_launch(void* const* d_in, const int* in_sizes, int n_in,
                              void* d_out, int out_size) {
    (void)in_sizes; (void)n_in; (void)out_size;
    const float* x            = (const float*)d_in[0];
    const float* weight       = (const float*)d_in[1];
    const float* input_weight = (const float*)d_in[2];
    const float* bias         = (const float*)d_in[3];
    const float* tau          = (const float*)d_in[4];
    float* out = (float*)d_out;

    w_prep_kernel<<<2 * NCH, 256>>>(weight, input_weight, tau);

    cudaFuncSetAttribute(fused_kernel, cudaFuncAttributeMaxDynamicSharedMemorySize,
                         SMEM_DYN);
    fused_kernel<<<ROWS / TM, NT, SMEM_DYN>>>(x, bias, out);
}